// round 2
// baseline (speedup 1.0000x reference)
#include <cuda_runtime.h>
#include <math.h>

#define Bb 2
#define Ss 2048
#define Dd 1024
#define Hh 16
#define DHh 64
#define IHh 4
#define IDd 64
#define TOPK 512
#define BT (Bb*Ss)

// ---------------- scratch (device globals; no allocation allowed) ----------
__device__ float g_qkv[BT * 3 * Dd];     // 50.3 MB  [b,s, 3D] (Q|K|V)
__device__ float g_iq[BT * IHh * IDd];   // 4.2 MB
__device__ float g_ik[BT * IDd];         // 1.05 MB
__device__ float g_iw[BT * IHh];
__device__ int   g_sel[BT * TOPK];       // selected key indices per (b,t)
__device__ int   g_cnt[BT];              // count (= min(t+1, 512))
__device__ float g_attn[BT * Dd];        // pre-W_o attention output

// ---------------- generic tiled SGEMM: C[M,N] = A[M,K] @ B[K,N] ------------
// 64x64 tile, 256 threads, 4x4 per thread. M multiple of 64, K multiple of 16.
__global__ __launch_bounds__(256) void sgemm(const float* __restrict__ A,
                                             const float* __restrict__ B,
                                             float* __restrict__ C,
                                             int M, int N, int K) {
    __shared__ float As[64][17];
    __shared__ float Bs[16][64];
    int tid = threadIdx.x;
    int tx = tid & 15, ty = tid >> 4;
    int row0 = blockIdx.y * 64, col0 = blockIdx.x * 64;
    float acc[4][4] = {};
    for (int k0 = 0; k0 < K; k0 += 16) {
        #pragma unroll
        for (int i = 0; i < 4; i++) {
            int idx = tid + i * 256;
            int r = idx >> 4, kk = idx & 15;
            As[r][kk] = A[(size_t)(row0 + r) * K + k0 + kk];
        }
        #pragma unroll
        for (int i = 0; i < 4; i++) {
            int idx = tid + i * 256;
            int kk = idx >> 6, c = idx & 63;
            int col = col0 + c;
            Bs[kk][c] = (col < N) ? B[(size_t)(k0 + kk) * N + col] : 0.f;
        }
        __syncthreads();
        #pragma unroll
        for (int kk = 0; kk < 16; kk++) {
            float a[4], b[4];
            #pragma unroll
            for (int i = 0; i < 4; i++) a[i] = As[ty * 4 + i][kk];
            #pragma unroll
            for (int j = 0; j < 4; j++) b[j] = Bs[kk][tx * 4 + j];
            #pragma unroll
            for (int i = 0; i < 4; i++)
                #pragma unroll
                for (int j = 0; j < 4; j++)
                    acc[i][j] += a[i] * b[j];
        }
        __syncthreads();
    }
    #pragma unroll
    for (int i = 0; i < 4; i++) {
        int r = row0 + ty * 4 + i;
        #pragma unroll
        for (int j = 0; j < 4; j++) {
            int c = col0 + tx * 4 + j;
            if (c < N) C[(size_t)r * N + c] = acc[i][j];
        }
    }
}

// ---------------- RoPE on Q and K in-place (interleaved pairs) -------------
__global__ __launch_bounds__(256) void rope_kernel(float* __restrict__ qkv) {
    int idx = blockIdx.x * blockDim.x + threadIdx.x;
    const int per = Bb * Ss * Hh * (DHh / 2);   // 2,097,152
    if (idx >= 2 * per) return;
    int which = (idx >= per) ? 1 : 0;           // 0=Q, 1=K
    int r = idx - which * per;
    int p = r & 31;  r >>= 5;
    int h = r & 15;  r >>= 4;
    int s = r & 2047; r >>= 11;
    int b = r;
    double theta = pow(10000.0, -(2.0 * p) / 64.0);
    float ang = (float)((double)s * theta);
    float sn, cn;
    sincosf(ang, &sn, &cn);
    size_t base = ((size_t)(b * Ss + s)) * (3 * Dd) + which * Dd + h * 64 + 2 * p;
    float x0 = qkv[base], x1 = qkv[base + 1];
    qkv[base]     = x0 * cn - x1 * sn;
    qkv[base + 1] = x1 * cn + x0 * sn;
}

__device__ __forceinline__ unsigned flipf(float f) {
    unsigned u = __float_as_uint(f);
    return (u & 0x80000000u) ? ~u : (u | 0x80000000u);
}

// ---------------- indexer scores + exact causal top-k ----------------------
// One block per (b,t), 256 threads.
__global__ __launch_bounds__(256) void indexer_topk(const float* __restrict__ iq,
                                                    const float* __restrict__ ik,
                                                    const float* __restrict__ iw,
                                                    int* __restrict__ sel,
                                                    int* __restrict__ cnt) {
    int bt = blockIdx.x;
    int b = bt >> 11, t = bt & 2047;
    int tid = threadIdx.x;
    int n = t + 1;

    __shared__ float sq[IHh * IDd];
    __shared__ float sw[IHh];
    if (tid < IHh * IDd) sq[tid] = iq[(size_t)bt * IHh * IDd + tid];
    if (tid < IHh) sw[tid] = iw[bt * IHh + tid];

    if (n <= TOPK) {
        for (int s = tid; s < n; s += 256) sel[(size_t)bt * TOPK + s] = s;
        if (tid == 0) cnt[bt] = n;
        return;
    }
    __syncthreads();

    __shared__ float sc[Ss];
    for (int s = tid; s < n; s += 256) {
        const float4* k4 = (const float4*)(ik + (size_t)(b * Ss + s) * IDd);
        float d0 = 0.f, d1 = 0.f, d2 = 0.f, d3 = 0.f;
        #pragma unroll
        for (int j4 = 0; j4 < 16; j4++) {
            float4 kv = k4[j4];
            int o = j4 * 4;
            d0 += sq[0*64+o]*kv.x + sq[0*64+o+1]*kv.y + sq[0*64+o+2]*kv.z + sq[0*64+o+3]*kv.w;
            d1 += sq[1*64+o]*kv.x + sq[1*64+o+1]*kv.y + sq[1*64+o+2]*kv.z + sq[1*64+o+3]*kv.w;
            d2 += sq[2*64+o]*kv.x + sq[2*64+o+1]*kv.y + sq[2*64+o+2]*kv.z + sq[2*64+o+3]*kv.w;
            d3 += sq[3*64+o]*kv.x + sq[3*64+o+1]*kv.y + sq[3*64+o+2]*kv.z + sq[3*64+o+3]*kv.w;
        }
        float score = sw[0]*fmaxf(d0,0.f) + sw[1]*fmaxf(d1,0.f)
                    + sw[2]*fmaxf(d2,0.f) + sw[3]*fmaxf(d3,0.f);
        sc[s] = score;
    }
    __syncthreads();

    // MSB radix select: find threshold key T and #equals to take (krem)
    __shared__ int hist[256];
    __shared__ unsigned sh_prefix;
    __shared__ int sh_krem;
    unsigned prefix = 0;
    int krem = TOPK;
    for (int pass = 0; pass < 4; pass++) {
        int shift = 24 - pass * 8;
        hist[tid] = 0;
        __syncthreads();
        for (int s = tid; s < n; s += 256) {
            unsigned key = flipf(sc[s]);
            if (((key >> shift) >> 8) == prefix)
                atomicAdd(&hist[(key >> shift) & 255], 1);
        }
        __syncthreads();
        if (tid == 0) {
            int cum = 0, bsel = 0;
            for (int bin = 255; bin >= 0; bin--) {
                int c = hist[bin];
                if (cum + c >= krem) { bsel = bin; break; }
                cum += c;
            }
            sh_prefix = (prefix << 8) | (unsigned)bsel;
            sh_krem = krem - cum;
        }
        __syncthreads();
        prefix = sh_prefix;
        krem = sh_krem;
        __syncthreads();
    }
    unsigned T = prefix;

    // write all strictly-greater
    __shared__ int nsel;
    if (tid == 0) nsel = 0;
    __syncthreads();
    for (int s = tid; s < n; s += 256) {
        if (flipf(sc[s]) > T) {
            int p = atomicAdd(&nsel, 1);
            sel[(size_t)bt * TOPK + p] = s;
        }
    }
    __syncthreads();

    // equals: take the krem SMALLEST indices (matches jax top_k tie-break)
    __shared__ int warpcnt[8];
    __shared__ int eqbase;
    if (tid == 0) eqbase = 0;
    __syncthreads();
    int lane = tid & 31, w = tid >> 5;
    for (int s0 = 0; s0 < n; s0 += 256) {
        int s = s0 + tid;
        bool eq = false;
        if (s < n) eq = (flipf(sc[s]) == T);
        unsigned bal = __ballot_sync(0xffffffffu, eq);
        if (lane == 0) warpcnt[w] = __popc(bal);
        __syncthreads();
        int wbase = 0;
        for (int i = 0; i < w; i++) wbase += warpcnt[i];
        int rank = eqbase + wbase + __popc(bal & ((1u << lane) - 1));
        if (eq && rank < krem) {
            int p = atomicAdd(&nsel, 1);
            sel[(size_t)bt * TOPK + p] = s;
        }
        __syncthreads();
        if (tid == 0) {
            int tot = 0;
            for (int i = 0; i < 8; i++) tot += warpcnt[i];
            eqbase += tot;
        }
        __syncthreads();
    }
    if (tid == 0) cnt[bt] = TOPK;
}

// ---------------- sparse SDPA: block per (b,t), warp per head --------------
__global__ __launch_bounds__(512) void sdpa(const float* __restrict__ qkv,
                                            const int* __restrict__ sel,
                                            const int* __restrict__ cnt,
                                            float* __restrict__ attn) {
    int bt = blockIdx.x;
    int b = bt >> 11;
    int tid = threadIdx.x;
    int w = tid >> 5, lane = tid & 31;
    int h = w;

    __shared__ float sQ[Hh * DHh];     // 4 KB
    __shared__ int   sSel[TOPK];       // 2 KB
    __shared__ float sL[Hh][TOPK];     // 32 KB

    int n = cnt[bt];
    const float* Qrow = qkv + (size_t)bt * 3 * Dd;
    for (int i = tid; i < Dd; i += 512) sQ[i] = Qrow[i];
    for (int i = tid; i < n; i += 512) sSel[i] = sel[(size_t)bt * TOPK + i];
    __syncthreads();

    const float scale = 0.125f;  // 1/sqrt(64)
    float q0 = sQ[h * 64 + lane * 2];
    float q1 = sQ[h * 64 + lane * 2 + 1];
    size_t batch_base = (size_t)b * Ss * 3 * Dd;

    // Phase A: logits
    #pragma unroll 2
    for (int j = 0; j < n; j++) {
        int s = sSel[j];
        const float2 kv = *(const float2*)(qkv + batch_base + (size_t)s * 3 * Dd + Dd + h * 64 + lane * 2);
        float d = q0 * kv.x + q1 * kv.y;
        #pragma unroll
        for (int o = 16; o; o >>= 1) d += __shfl_xor_sync(0xffffffffu, d, o);
        if (lane == 0) sL[h][j] = d * scale;
    }
    __syncwarp();

    // Phase B: softmax (per head, warp-local)
    float m = -1e30f;
    for (int j = lane; j < n; j += 32) m = fmaxf(m, sL[h][j]);
    #pragma unroll
    for (int o = 16; o; o >>= 1) m = fmaxf(m, __shfl_xor_sync(0xffffffffu, m, o));
    float sum = 0.f;
    for (int j = lane; j < n; j += 32) {
        float p = __expf(sL[h][j] - m);
        sL[h][j] = p;
        sum += p;
    }
    #pragma unroll
    for (int o = 16; o; o >>= 1) sum += __shfl_xor_sync(0xffffffffu, sum, o);
    float inv = 1.f / sum;
    __syncwarp();

    // Phase C: P @ V
    float a0 = 0.f, a1 = 0.f;
    #pragma unroll 2
    for (int j = 0; j < n; j++) {
        float p = sL[h][j];
        int s = sSel[j];
        const float2 v = *(const float2*)(qkv + batch_base + (size_t)s * 3 * Dd + 2 * Dd + h * 64 + lane * 2);
        a0 += p * v.x;
        a1 += p * v.y;
    }
    size_t ob = (size_t)bt * Dd + h * 64 + lane * 2;
    attn[ob]     = a0 * inv;
    attn[ob + 1] = a1 * inv;
}

// ---------------- launch ----------------------------------------------------
extern "C" void kernel_launch(void* const* d_in, const int* in_sizes, int n_in,
                              void* d_out, int out_size) {
    const float* x      = (const float*)d_in[0];
    const float* W_qkv  = (const float*)d_in[1];
    const float* W_o    = (const float*)d_in[2];
    const float* Wq_idx = (const float*)d_in[3];
    const float* Wk_idx = (const float*)d_in[4];
    const float* Ww_idx = (const float*)d_in[5];
    float* out = (float*)d_out;

    float *qkv, *iq, *ik, *iw, *attn;
    int *sel, *cnt;
    cudaGetSymbolAddress((void**)&qkv,  g_qkv);
    cudaGetSymbolAddress((void**)&iq,   g_iq);
    cudaGetSymbolAddress((void**)&ik,   g_ik);
    cudaGetSymbolAddress((void**)&iw,   g_iw);
    cudaGetSymbolAddress((void**)&attn, g_attn);
    cudaGetSymbolAddress((void**)&sel,  g_sel);
    cudaGetSymbolAddress((void**)&cnt,  g_cnt);

    const int M = BT;  // 4096

    // QKV projection
    sgemm<<<dim3(3 * Dd / 64, M / 64), 256>>>(x, W_qkv, qkv, M, 3 * Dd, Dd);
    // RoPE on Q and K
    rope_kernel<<<(2 * Bb * Ss * Hh * 32 + 255) / 256, 256>>>(qkv);
    // indexer projections
    sgemm<<<dim3(IHh * IDd / 64, M / 64), 256>>>(x, Wq_idx, iq, M, IHh * IDd, Dd);
    sgemm<<<dim3(1, M / 64), 256>>>(x, Wk_idx, ik, M, IDd, Dd);
    sgemm<<<dim3(1, M / 64), 256>>>(x, Ww_idx, iw, M, IHh, Dd);
    // indexer scores + top-k selection
    indexer_topk<<<BT, 256>>>(iq, ik, iw, sel, cnt);
    // sparse attention
    sdpa<<<BT, 512>>>(qkv, sel, cnt, attn);
    // output projection
    sgemm<<<dim3(Dd / 64, M / 64), 256>>>(attn, W_o, out, M, Dd, Dd);
}